// round 15
// baseline (speedup 1.0000x reference)
#include <cuda_runtime.h>
#include <cstdint>

#define NT 16     // NUM_TYPES
#define OD 128    // OUT_DIM
#define N_MAX 100000
#define TILE_N 64 // nodes staged per block iteration in k_final

typedef unsigned long long u64;

// Packed fp32x2 FMA (Blackwell FFMA2): d = a*b + c, two fp32 lanes per issue.
#define FMA2(d, a, b, c) \
    asm("fma.rn.f32x2 %0, %1, %2, %3;" : "=l"(d) : "l"(a), "l"(b), "l"(c))
#define PACK2(out, lo, hi) \
    asm("mov.b64 %0, {%1, %2};" : "=l"(out) : "f"(lo), "f"(hi))
#define UNPACK2(lo, hi, in) \
    asm("mov.b64 {%0, %1}, %2;" : "=f"(lo), "=f"(hi) : "l"(in))

// Scratch (allocation-free rule: __device__ globals). 16B-aligned for float4.
// g_p is stored PERMUTED within each 16-float row: position q*4+j holds
// logical element q+4j (q=0..3). Scatter lane q loads float4 #q =
// {p[q], p[q+4], p[q+8], p[q+12]} and REDs to natural msum positions q+4j;
// RED #j across the 4 lanes covers 16 CONTIGUOUS bytes (validated R8).
__device__ __align__(16) float g_p[N_MAX * NT];
__device__ __align__(16) float g_msum[N_MAX * NT];   // natural layout
__device__ int g_idx64;   // 1 if indices are int64, 0 if int32

// ---------------------------------------------------------------------------
// p = softmax(relu(r@W1+b1) @ Wp + bp)   ONE node per thread (782 blocks ->
// ~21 warps/SM, 2x R14 occupancy), z dot-product split into TWO independent
// 4-deep FFMA2 chains (ILP-2). Prologue fuses init: zero msum + detect width.
// Output stored in the q/4-permuted layout (see g_p comment).
// ---------------------------------------------------------------------------
__global__ void __launch_bounds__(128) k_compute_p(
        const float* __restrict__ r,
        const float* __restrict__ W1,
        const float* __restrict__ b1,
        const float* __restrict__ Wp,
        const float* __restrict__ bp,
        const void* __restrict__ src,
        int E, int n) {
    int gid = blockIdx.x * blockDim.x + threadIdx.x;
    int gtot = gridDim.x * blockDim.x;

    // --- fused init ---
    if (gid == 0) {
        const unsigned long long* p = (const unsigned long long*)src;
        int is64 = 1;
        int lim = (E / 2 < 16) ? E / 2 : 16;
        for (int k = 0; k < lim; k++) {
            if (p[k] > 0x7FFFFFFFULL) is64 = 0;
        }
        g_idx64 = is64;
    }
    for (int i = gid; i < n * 4; i += gtot)
        ((float4*)g_msum)[i] = make_float4(0.f, 0.f, 0.f, 0.f);

    __shared__ __align__(16) float sW1t[OD * NT];  // [j*16 + k] = W1[k*128 + j]
    __shared__ __align__(16) float sWp [OD * NT];  // [j*16 + t] = Wp[j*16 + t]
    __shared__ float sb1 [OD];
    __shared__ float sbp [NT];

    for (int i = threadIdx.x; i < OD * NT; i += blockDim.x) {
        int j = i >> 4, k = i & 15;
        sW1t[i] = W1[k * OD + j];
        sWp[i]  = Wp[i];
    }
    for (int i = threadIdx.x; i < OD; i += blockDim.x) sb1[i] = b1[i];
    if (threadIdx.x < NT) sbp[threadIdx.x] = bp[threadIdx.x];
    __syncthreads();

    int node = gid;
    if (node >= n) return;

    // r row pre-packed over k: rA2[i] = (r[2i], r[2i+1])
    u64 rA2[8];
    {
        const float4* rp = (const float4*)(r + (size_t)node * NT);
#pragma unroll
        for (int i = 0; i < 4; i++) {
            float4 v = rp[i];
            PACK2(rA2[i * 2 + 0], v.x, v.y);
            PACK2(rA2[i * 2 + 1], v.z, v.w);
        }
    }

    // accumulators packed over t: acc2[i] = (acc[2i], acc[2i+1]), init = bp
    u64 acc2[8];
#pragma unroll
    for (int i = 0; i < 8; i++) {
        PACK2(acc2[i], sbp[2 * i], sbp[2 * i + 1]);
    }

#pragma unroll 4
    for (int j = 0; j < OD; j++) {
        // W1t row j: 16 floats = 8 packed k-pairs (uniform broadcast LDS.128)
        const longlong2* w1p = (const longlong2*)(sW1t + j * NT);
        longlong2 wA = w1p[0], wB = w1p[1], wC = w1p[2], wD = w1p[3];

        // TWO independent 4-deep chains (ILP-2)
        u64 za = 0ULL, zb = 0ULL;
        FMA2(za, rA2[0], (u64)wA.x, za);  FMA2(zb, rA2[4], (u64)wC.x, zb);
        FMA2(za, rA2[1], (u64)wA.y, za);  FMA2(zb, rA2[5], (u64)wC.y, zb);
        FMA2(za, rA2[2], (u64)wB.x, za);  FMA2(zb, rA2[6], (u64)wD.x, zb);
        FMA2(za, rA2[3], (u64)wB.y, za);  FMA2(zb, rA2[7], (u64)wD.y, zb);

        float al, ah, bl, bh;
        UNPACK2(al, ah, za);
        UNPACK2(bl, bh, zb);
        float z = fmaxf(((al + ah) + (bl + bh)) + sb1[j], 0.0f);
        u64 zz;
        PACK2(zz, z, z);

        // Wp row j: 16 floats = 8 packed t-pairs; 8 INDEPENDENT chains
        const longlong2* wpp = (const longlong2*)(sWp + j * NT);
        longlong2 pA = wpp[0], pB = wpp[1], pC = wpp[2], pD = wpp[3];

        FMA2(acc2[0], zz, (u64)pA.x, acc2[0]);
        FMA2(acc2[1], zz, (u64)pA.y, acc2[1]);
        FMA2(acc2[2], zz, (u64)pB.x, acc2[2]);
        FMA2(acc2[3], zz, (u64)pB.y, acc2[3]);
        FMA2(acc2[4], zz, (u64)pC.x, acc2[4]);
        FMA2(acc2[5], zz, (u64)pC.y, acc2[5]);
        FMA2(acc2[6], zz, (u64)pD.x, acc2[6]);
        FMA2(acc2[7], zz, (u64)pD.y, acc2[7]);
    }

    float acc[NT];
#pragma unroll
    for (int i = 0; i < 8; i++) {
        UNPACK2(acc[2 * i], acc[2 * i + 1], acc2[i]);
    }

    float m = acc[0];
#pragma unroll
    for (int t = 1; t < NT; t++) m = fmaxf(m, acc[t]);
    float s = 0.0f;
#pragma unroll
    for (int t = 0; t < NT; t++) { acc[t] = __expf(acc[t] - m); s += acc[t]; }
    float inv = 1.0f / s;
    float4* o = (float4*)(g_p + (size_t)node * NT);
    // PERMUTED store: float4 #q = {p[q], p[q+4], p[q+8], p[q+12]}
    o[0] = make_float4(acc[0]*inv, acc[4]*inv, acc[8]*inv,  acc[12]*inv);
    o[1] = make_float4(acc[1]*inv, acc[5]*inv, acc[9]*inv,  acc[13]*inv);
    o[2] = make_float4(acc[2]*inv, acc[6]*inv, acc[10]*inv, acc[14]*inv);
    o[3] = make_float4(acc[3]*inv, acc[7]*inv, acc[11]*inv, acc[15]*inv);
}

// ---------------------------------------------------------------------------
// Scatter: msum[dst] += p[src].  4 lanes per edge, 2 edges per thread
// (validated R10/R13). RED #j across an edge's 4 lanes covers 16 contiguous
// bytes. No degree atomics (row-sum trick).
// ---------------------------------------------------------------------------
__global__ void k_scatter(const void* __restrict__ srcv,
                          const void* __restrict__ dstv,
                          int E, int n) {
    int gid = blockIdx.x * blockDim.x + threadIdx.x;
    int pair = gid >> 2;
    int e0 = pair * 2;
    if (e0 >= E) return;
    int q = gid & 3;
    bool has2 = (e0 + 1 < E);

    int s0, d0, s1 = 0, d1 = 0;
    if (g_idx64) {
        const longlong2* ps = (const longlong2*)srcv;
        const longlong2* pd = (const longlong2*)dstv;
        longlong2 sv = ps[pair];
        longlong2 dv = pd[pair];
        s0 = (int)sv.x; s1 = (int)sv.y;
        d0 = (int)dv.x; d1 = (int)dv.y;
    } else {
        const int2* ps = (const int2*)srcv;
        const int2* pd = (const int2*)dstv;
        int2 sv = ps[pair];
        int2 dv = pd[pair];
        s0 = sv.x; s1 = sv.y;
        d0 = dv.x; d1 = dv.y;
    }
    s0 = min(max(s0, 0), n - 1);
    d0 = min(max(d0, 0), n - 1);

    const float4 v0 = __ldg((const float4*)(g_p + (size_t)s0 * NT + q * 4));
    float* row0 = g_msum + (size_t)d0 * NT + q;
    atomicAdd(row0 + 0,  v0.x);
    atomicAdd(row0 + 4,  v0.y);
    atomicAdd(row0 + 8,  v0.z);
    atomicAdd(row0 + 12, v0.w);

    if (has2) {
        s1 = min(max(s1, 0), n - 1);
        d1 = min(max(d1, 0), n - 1);
        const float4 v1 = __ldg((const float4*)(g_p + (size_t)s1 * NT + q * 4));
        float* row1 = g_msum + (size_t)d1 * NT + q;
        atomicAdd(row1 + 0,  v1.x);
        atomicAdd(row1 + 4,  v1.y);
        atomicAdd(row1 + 8,  v1.z);
        atomicAdd(row1 + 12, v1.w);
    }
}

// ---------------------------------------------------------------------------
// out = relu(invd * (msum @ Wf) + bf)  with invd = 1/max(round(rowsum),1).
// smem staging (validated R14): block stages TILE_N=64 msum rows coalesced,
// 4-lane butterfly row sums -> sinv[]; compute from broadcast LDS; coalesced
// stores. Normalization folded in by linearity (no k_norm kernel).
// ---------------------------------------------------------------------------
__global__ void __launch_bounds__(256) k_final(
        const float* __restrict__ Wf,
        const float* __restrict__ bf,
        float* __restrict__ out,
        int n) {
    __shared__ __align__(16) float srow[TILE_N * NT];   // 4KB
    __shared__ float sinv[TILE_N];

    int tid = threadIdx.x;
    int j   = tid & 127;
    int sub = tid >> 7;          // 0 or 1

    u64 w2[8];
#pragma unroll
    for (int i = 0; i < 8; i++) {
        PACK2(w2[i], Wf[(2 * i) * OD + j], Wf[(2 * i + 1) * OD + j]);
    }
    float bj = bf[j];

    int ntiles = (n + TILE_N - 1) / TILE_N;
    for (int tile = blockIdx.x; tile < ntiles; tile += gridDim.x) {
        int base   = tile * TILE_N;
        int nnodes = min(TILE_N, n - base);

        if (tid < nnodes * 4) {
            float4 v = ((const float4*)(g_msum + (size_t)base * NT))[tid];
            ((float4*)srow)[tid] = v;
            float s = (v.x + v.y) + (v.z + v.w);
            s += __shfl_xor_sync(0xffffffffu, s, 1);
            s += __shfl_xor_sync(0xffffffffu, s, 2);
            if ((tid & 3) == 0)
                sinv[tid >> 2] = 1.0f / fmaxf(nearbyintf(s), 1.0f);
        }
        __syncthreads();

        for (int nn = sub; nn < nnodes; nn += 2) {
            const longlong2* rw = (const longlong2*)(srow + nn * NT);
            longlong2 a0 = rw[0], a1 = rw[1], a2 = rw[2], a3 = rw[3];

            u64 acc = 0ULL;
            FMA2(acc, (u64)a0.x, w2[0], acc);
            FMA2(acc, (u64)a0.y, w2[1], acc);
            FMA2(acc, (u64)a1.x, w2[2], acc);
            FMA2(acc, (u64)a1.y, w2[3], acc);
            FMA2(acc, (u64)a2.x, w2[4], acc);
            FMA2(acc, (u64)a2.y, w2[5], acc);
            FMA2(acc, (u64)a3.x, w2[6], acc);
            FMA2(acc, (u64)a3.y, w2[7], acc);
            float al, ah;
            UNPACK2(al, ah, acc);
            float v = fmaf(sinv[nn], al + ah, bj);
            out[(size_t)(base + nn) * OD + j] = fmaxf(v, 0.0f);
        }
        __syncthreads();
    }
}

// ---------------------------------------------------------------------------
// Inputs (metadata order): r, src, dst, W1, b1, Wp, bp, Wf, bf
// ---------------------------------------------------------------------------
extern "C" void kernel_launch(void* const* d_in, const int* in_sizes, int n_in,
                              void* d_out, int out_size) {
    const float* r   = (const float*)d_in[0];
    const void*  src = d_in[1];
    const void*  dst = d_in[2];
    const float* W1  = (const float*)d_in[3];
    const float* b1  = (const float*)d_in[4];
    const float* Wp  = (const float*)d_in[5];
    const float* bp  = (const float*)d_in[6];
    const float* Wf  = (const float*)d_in[7];
    const float* bf  = (const float*)d_in[8];
    float*       out = (float*)d_out;

    int n = in_sizes[0] / NT;
    int E = in_sizes[1];
    if (n > N_MAX) n = N_MAX;

    k_compute_p<<<(n + 127) / 128, 128>>>(r, W1, b1, Wp, bp, src, E, n);
    {
        long long threads = (long long)((E + 1) / 2) * 4;
        int blocks = (int)((threads + 255) / 256);
        k_scatter<<<blocks, 256>>>(src, dst, E, n);
    }
    {
        int ntiles = (n + TILE_N - 1) / TILE_N;
        int blocks = min(ntiles, 1184);   // 8 blocks/SM x 148 SMs
        k_final<<<blocks, 256>>>(Wf, bf, out, n);
    }
}

// round 17
// speedup vs baseline: 1.0687x; 1.0687x over previous
#include <cuda_runtime.h>
#include <cstdint>

#define NT 16     // NUM_TYPES
#define OD 128    // OUT_DIM
#define N_MAX 100000
#define TILE_N 64 // nodes staged per block iteration in k_final

typedef unsigned long long u64;
typedef unsigned int u32;

#define FIX_S   4194304.0f          // 2^22
#define FIX_INV (1.0f / 4194304.0f)

// Packed fp32x2 FMA (Blackwell FFMA2): d = a*b + c, two fp32 lanes per issue.
#define FMA2(d, a, b, c) \
    asm("fma.rn.f32x2 %0, %1, %2, %3;" : "=l"(d) : "l"(a), "l"(b), "l"(c))
#define PACK2(out, lo, hi) \
    asm("mov.b64 %0, {%1, %2};" : "=l"(out) : "f"(lo), "f"(hi))
#define UNPACK2(lo, hi, in) \
    asm("mov.b64 {%0, %1}, %2;" : "=f"(lo), "=f"(hi) : "l"(in))

// Scratch (allocation-free rule: __device__ globals). 16B-aligned.
// g_p: per node, 8 u64 entries. Logical entry i packs fixed-point
// (p[i] in low 32, p[i+8] in high 32), scaled by FIX_S. Row position order
// is [e0,e4, e1,e5, e2,e6, e3,e7] so scatter lane q's ulonglong2 load at
// position 2q yields entries {q, q+4}; RED #0 across lanes covers
// msum entries 0..3 (32 contiguous bytes), RED #1 covers 4..7.
// g_msum: entry i at NATURAL position i (same per-entry packing).
__device__ __align__(16) u64 g_p[N_MAX * 8];
__device__ __align__(16) u64 g_msum[N_MAX * 8];
__device__ int g_idx64;   // 1 if indices are int64, 0 if int32

// ---------------------------------------------------------------------------
// p = softmax(relu(r@W1+b1) @ Wp + bp)   TWO nodes per thread, 64-thr blocks
// (782 blocks -> balanced SM distribution). FFMA2 ILP-2 chains (R11/R13).
// Prologue fuses init: zero msum + detect idx width. Output stored as packed
// fixed-point u64 (see g_p comment).
// ---------------------------------------------------------------------------
__global__ void __launch_bounds__(64) k_compute_p(
        const float* __restrict__ r,
        const float* __restrict__ W1,
        const float* __restrict__ b1,
        const float* __restrict__ Wp,
        const float* __restrict__ bp,
        const void* __restrict__ src,
        int E, int n) {
    int gid = blockIdx.x * blockDim.x + threadIdx.x;
    int gtot = gridDim.x * blockDim.x;

    // --- fused init ---
    if (gid == 0) {
        const unsigned long long* p = (const unsigned long long*)src;
        int is64 = 1;
        int lim = (E / 2 < 16) ? E / 2 : 16;
        for (int k = 0; k < lim; k++) {
            if (p[k] > 0x7FFFFFFFULL) is64 = 0;
        }
        g_idx64 = is64;
    }
    for (int i = gid; i < n * 4; i += gtot)
        ((float4*)g_msum)[i] = make_float4(0.f, 0.f, 0.f, 0.f);

    __shared__ __align__(16) float sW1t[OD * NT];  // [j*16 + k] = W1[k*128 + j]
    __shared__ __align__(16) float sWp [OD * NT];  // [j*16 + t] = Wp[j*16 + t]
    __shared__ float sb1 [OD];
    __shared__ float sbp [NT];

    for (int i = threadIdx.x; i < OD * NT; i += blockDim.x) {
        int j = i >> 4, k = i & 15;
        sW1t[i] = W1[k * OD + j];
        sWp[i]  = Wp[i];
    }
    for (int i = threadIdx.x; i < OD; i += blockDim.x) sb1[i] = b1[i];
    if (threadIdx.x < NT) sbp[threadIdx.x] = bp[threadIdx.x];
    __syncthreads();

    int node0 = gid * 2;
    if (node0 >= n) return;
    bool two = (node0 + 1 < n);

    u64 rA2[8], rB2[8];
    {
        const float4* rp0 = (const float4*)(r + (size_t)node0 * NT);
#pragma unroll
        for (int i = 0; i < 4; i++) {
            float4 v = rp0[i];
            PACK2(rA2[i * 2 + 0], v.x, v.y);
            PACK2(rA2[i * 2 + 1], v.z, v.w);
        }
        if (two) {
            const float4* rp1 = (const float4*)(r + (size_t)(node0 + 1) * NT);
#pragma unroll
            for (int i = 0; i < 4; i++) {
                float4 v = rp1[i];
                PACK2(rB2[i * 2 + 0], v.x, v.y);
                PACK2(rB2[i * 2 + 1], v.z, v.w);
            }
        } else {
#pragma unroll
            for (int i = 0; i < 8; i++) rB2[i] = 0ULL;
        }
    }

    u64 accA2[8], accB2[8];
#pragma unroll
    for (int i = 0; i < 8; i++) {
        u64 b2; PACK2(b2, sbp[2 * i], sbp[2 * i + 1]);
        accA2[i] = b2; accB2[i] = b2;
    }

#pragma unroll 2
    for (int j = 0; j < OD; j++) {
        const longlong2* w1p = (const longlong2*)(sW1t + j * NT);
        longlong2 wA = w1p[0], wB = w1p[1], wC = w1p[2], wD = w1p[3];

        u64 zA2 = 0ULL, zB2 = 0ULL;
        FMA2(zA2, rA2[0], (u64)wA.x, zA2); FMA2(zB2, rB2[0], (u64)wA.x, zB2);
        FMA2(zA2, rA2[1], (u64)wA.y, zA2); FMA2(zB2, rB2[1], (u64)wA.y, zB2);
        FMA2(zA2, rA2[2], (u64)wB.x, zA2); FMA2(zB2, rB2[2], (u64)wB.x, zB2);
        FMA2(zA2, rA2[3], (u64)wB.y, zA2); FMA2(zB2, rB2[3], (u64)wB.y, zB2);
        FMA2(zA2, rA2[4], (u64)wC.x, zA2); FMA2(zB2, rB2[4], (u64)wC.x, zB2);
        FMA2(zA2, rA2[5], (u64)wC.y, zA2); FMA2(zB2, rB2[5], (u64)wC.y, zB2);
        FMA2(zA2, rA2[6], (u64)wD.x, zA2); FMA2(zB2, rB2[6], (u64)wD.x, zB2);
        FMA2(zA2, rA2[7], (u64)wD.y, zA2); FMA2(zB2, rB2[7], (u64)wD.y, zB2);

        float bj = sb1[j];
        float zAl, zAh, zBl, zBh;
        UNPACK2(zAl, zAh, zA2);
        UNPACK2(zBl, zBh, zB2);
        float zA = fmaxf((zAl + zAh) + bj, 0.0f);
        float zB = fmaxf((zBl + zBh) + bj, 0.0f);
        u64 zzA, zzB;
        PACK2(zzA, zA, zA);
        PACK2(zzB, zB, zB);

        const longlong2* wpp = (const longlong2*)(sWp + j * NT);
        longlong2 pA = wpp[0], pB = wpp[1], pC = wpp[2], pD = wpp[3];

        FMA2(accA2[0], zzA, (u64)pA.x, accA2[0]); FMA2(accB2[0], zzB, (u64)pA.x, accB2[0]);
        FMA2(accA2[1], zzA, (u64)pA.y, accA2[1]); FMA2(accB2[1], zzB, (u64)pA.y, accB2[1]);
        FMA2(accA2[2], zzA, (u64)pB.x, accA2[2]); FMA2(accB2[2], zzB, (u64)pB.x, accB2[2]);
        FMA2(accA2[3], zzA, (u64)pB.y, accA2[3]); FMA2(accB2[3], zzB, (u64)pB.y, accB2[3]);
        FMA2(accA2[4], zzA, (u64)pC.x, accA2[4]); FMA2(accB2[4], zzB, (u64)pC.x, accB2[4]);
        FMA2(accA2[5], zzA, (u64)pC.y, accA2[5]); FMA2(accB2[5], zzB, (u64)pC.y, accB2[5]);
        FMA2(accA2[6], zzA, (u64)pD.x, accA2[6]); FMA2(accB2[6], zzB, (u64)pD.x, accB2[6]);
        FMA2(accA2[7], zzA, (u64)pD.y, accA2[7]); FMA2(accB2[7], zzB, (u64)pD.y, accB2[7]);
    }

    float accA[NT], accB[NT];
#pragma unroll
    for (int i = 0; i < 8; i++) {
        UNPACK2(accA[2 * i], accA[2 * i + 1], accA2[i]);
        UNPACK2(accB[2 * i], accB[2 * i + 1], accB2[i]);
    }

    // softmax + fixed-point pack + store (both nodes)
    {
        float m = accA[0];
#pragma unroll
        for (int t = 1; t < NT; t++) m = fmaxf(m, accA[t]);
        float s = 0.0f;
#pragma unroll
        for (int t = 0; t < NT; t++) { accA[t] = __expf(accA[t] - m); s += accA[t]; }
        float sc = FIX_S / s;
        u32 f[NT];
#pragma unroll
        for (int t = 0; t < NT; t++) f[t] = __float2uint_rn(accA[t] * sc);
        u64 e[8];
#pragma unroll
        for (int i = 0; i < 8; i++) e[i] = (u64)f[i] | ((u64)f[i + 8] << 32);
        ulonglong2* o = (ulonglong2*)(g_p + (size_t)node0 * 8);
        o[0] = make_ulonglong2(e[0], e[4]);
        o[1] = make_ulonglong2(e[1], e[5]);
        o[2] = make_ulonglong2(e[2], e[6]);
        o[3] = make_ulonglong2(e[3], e[7]);
    }
    if (two) {
        float m = accB[0];
#pragma unroll
        for (int t = 1; t < NT; t++) m = fmaxf(m, accB[t]);
        float s = 0.0f;
#pragma unroll
        for (int t = 0; t < NT; t++) { accB[t] = __expf(accB[t] - m); s += accB[t]; }
        float sc = FIX_S / s;
        u32 f[NT];
#pragma unroll
        for (int t = 0; t < NT; t++) f[t] = __float2uint_rn(accB[t] * sc);
        u64 e[8];
#pragma unroll
        for (int i = 0; i < 8; i++) e[i] = (u64)f[i] | ((u64)f[i + 8] << 32);
        ulonglong2* o = (ulonglong2*)(g_p + (size_t)(node0 + 1) * 8);
        o[0] = make_ulonglong2(e[0], e[4]);
        o[1] = make_ulonglong2(e[1], e[5]);
        o[2] = make_ulonglong2(e[2], e[6]);
        o[3] = make_ulonglong2(e[3], e[7]);
    }
}

// ---------------------------------------------------------------------------
// Scatter: msum[dst] += p[src] in packed fixed-point.  4 lanes per edge,
// 2 edges per thread. Lane q: one 16B gather (entries q, q+4) + TWO u64
// REDs -> 8 REDs/edge total (HALF of the f32 version's 16). RED #0 across
// lanes covers msum entries 0..3 = 32 contiguous bytes; RED #1 entries 4..7.
// ---------------------------------------------------------------------------
__global__ void k_scatter(const void* __restrict__ srcv,
                          const void* __restrict__ dstv,
                          int E, int n) {
    int gid = blockIdx.x * blockDim.x + threadIdx.x;
    int pair = gid >> 2;
    int e0 = pair * 2;
    if (e0 >= E) return;
    int q = gid & 3;
    bool has2 = (e0 + 1 < E);

    int s0, d0, s1 = 0, d1 = 0;
    if (g_idx64) {
        const longlong2* ps = (const longlong2*)srcv;
        const longlong2* pd = (const longlong2*)dstv;
        longlong2 sv = ps[pair];
        longlong2 dv = pd[pair];
        s0 = (int)sv.x; s1 = (int)sv.y;
        d0 = (int)dv.x; d1 = (int)dv.y;
    } else {
        const int2* ps = (const int2*)srcv;
        const int2* pd = (const int2*)dstv;
        int2 sv = ps[pair];
        int2 dv = pd[pair];
        s0 = sv.x; s1 = sv.y;
        d0 = dv.x; d1 = dv.y;
    }
    s0 = min(max(s0, 0), n - 1);
    d0 = min(max(d0, 0), n - 1);

    const ulonglong2 v0 = __ldg((const ulonglong2*)(g_p + (size_t)s0 * 8) + q);
    u64* row0 = g_msum + (size_t)d0 * 8;
    atomicAdd(row0 + q,     v0.x);   // entry q     (RED #0: 32B contiguous)
    atomicAdd(row0 + 4 + q, v0.y);   // entry q+4   (RED #1: 32B contiguous)

    if (has2) {
        s1 = min(max(s1, 0), n - 1);
        d1 = min(max(d1, 0), n - 1);
        const ulonglong2 v1 = __ldg((const ulonglong2*)(g_p + (size_t)s1 * 8) + q);
        u64* row1 = g_msum + (size_t)d1 * 8;
        atomicAdd(row1 + q,     v1.x);
        atomicAdd(row1 + 4 + q, v1.y);
    }
}

// ---------------------------------------------------------------------------
// out = relu(invd * (n_sum @ Wf) + bf),  invd = 1/(S * max(round(sum/S),1)).
// smem staging (R14 pattern). msum is NATURAL entry order, so ulonglong2
// #pp = entries (2pp, 2pp+1); entry i = (t=i low, t=i+8 high). Unpack:
//   v.x -> t=2pp, t=2pp+8 ;  v.y -> t=2pp+1, t=2pp+9.   (R16 bug was here.)
// Compute loop identical to validated R14: broadcast LDS + 8 FFMA2.
// ---------------------------------------------------------------------------
__global__ void __launch_bounds__(256) k_final(
        const float* __restrict__ Wf,
        const float* __restrict__ bf,
        float* __restrict__ out,
        int n) {
    __shared__ __align__(16) float srow[TILE_N * NT];   // 4KB, natural layout
    __shared__ float sinv[TILE_N];

    int tid = threadIdx.x;
    int j   = tid & 127;
    int sub = tid >> 7;          // 0 or 1

    u64 w2[8];
#pragma unroll
    for (int i = 0; i < 8; i++) {
        PACK2(w2[i], Wf[(2 * i) * OD + j], Wf[(2 * i + 1) * OD + j]);
    }
    float bj = bf[j];

    int ntiles = (n + TILE_N - 1) / TILE_N;
    for (int tile = blockIdx.x; tile < ntiles; tile += gridDim.x) {
        int base   = tile * TILE_N;
        int nnodes = min(TILE_N, n - base);

        // stage: thread tid loads ulonglong2 #(tid&3) of node base+(tid>>2)
        // (coalesced 16B), unpacks 4 fixed values -> natural srow positions.
        if (tid < nnodes * 4) {
            ulonglong2 v = ((const ulonglong2*)(g_msum + (size_t)base * 8))[tid];
            int nn = tid >> 2, pp = tid & 3;
            // v.x = entry 2pp   -> (t=2pp,   t=2pp+8)
            // v.y = entry 2pp+1 -> (t=2pp+1, t=2pp+9)
            float f0 = __uint2float_rn((u32)(v.x));
            float f1 = __uint2float_rn((u32)(v.x >> 32));
            float f2 = __uint2float_rn((u32)(v.y));
            float f3 = __uint2float_rn((u32)(v.y >> 32));
            float* row = srow + nn * NT;
            row[2 * pp]     = f0;
            row[2 * pp + 8] = f1;
            row[2 * pp + 1] = f2;
            row[2 * pp + 9] = f3;
            float s = (f0 + f1) + (f2 + f3);
            s += __shfl_xor_sync(0xffffffffu, s, 1);
            s += __shfl_xor_sync(0xffffffffu, s, 2);
            if (pp == 0) {
                float deg = nearbyintf(s * FIX_INV);
                sinv[nn] = FIX_INV / fmaxf(deg, 1.0f);
            }
        }
        __syncthreads();

        for (int nn = sub; nn < nnodes; nn += 2) {
            const longlong2* rw = (const longlong2*)(srow + nn * NT);
            longlong2 a0 = rw[0], a1 = rw[1], a2 = rw[2], a3 = rw[3];

            u64 acc = 0ULL;
            FMA2(acc, (u64)a0.x, w2[0], acc);
            FMA2(acc, (u64)a0.y, w2[1], acc);
            FMA2(acc, (u64)a1.x, w2[2], acc);
            FMA2(acc, (u64)a1.y, w2[3], acc);
            FMA2(acc, (u64)a2.x, w2[4], acc);
            FMA2(acc, (u64)a2.y, w2[5], acc);
            FMA2(acc, (u64)a3.x, w2[6], acc);
            FMA2(acc, (u64)a3.y, w2[7], acc);
            float al, ah;
            UNPACK2(al, ah, acc);
            float v = fmaf(sinv[nn], al + ah, bj);
            out[(size_t)(base + nn) * OD + j] = fmaxf(v, 0.0f);
        }
        __syncthreads();
    }
}

// ---------------------------------------------------------------------------
// Inputs (metadata order): r, src, dst, W1, b1, Wp, bp, Wf, bf
// ---------------------------------------------------------------------------
extern "C" void kernel_launch(void* const* d_in, const int* in_sizes, int n_in,
                              void* d_out, int out_size) {
    const float* r   = (const float*)d_in[0];
    const void*  src = d_in[1];
    const void*  dst = d_in[2];
    const float* W1  = (const float*)d_in[3];
    const float* b1  = (const float*)d_in[4];
    const float* Wp  = (const float*)d_in[5];
    const float* bp  = (const float*)d_in[6];
    const float* Wf  = (const float*)d_in[7];
    const float* bf  = (const float*)d_in[8];
    float*       out = (float*)d_out;

    int n = in_sizes[0] / NT;
    int E = in_sizes[1];
    if (n > N_MAX) n = N_MAX;

    k_compute_p<<<((n + 1) / 2 + 63) / 64, 64>>>(r, W1, b1, Wp, bp, src, E, n);
    {
        long long threads = (long long)((E + 1) / 2) * 4;
        int blocks = (int)((threads + 255) / 256);
        k_scatter<<<blocks, 256>>>(src, dst, E, n);
    }
    {
        int ntiles = (n + TILE_N - 1) / TILE_N;
        int blocks = min(ntiles, 1184);   // 8 blocks/SM x 148 SMs
        k_final<<<blocks, 256>>>(Wf, bf, out, n);
    }
}